// round 1
// baseline (speedup 1.0000x reference)
#include <cuda_runtime.h>

#define SEQ  4096
#define DIM  768
#define NH   12
#define HD   64

// Scratch (device globals: allocation-free per harness rules)
__device__ float g_qkv[3 * NH * SEQ * HD];   // [which][head][n][d]
__device__ float g_attn[SEQ * DIM];          // [n][h*64+d]

// ----------------------------------------------------------------------------
// SGEMM (NT): C[M,N] = A[M,K] @ B[N,K]^T + bias
// BM=BN=128, BK=16, 256 threads, 8x8 per-thread microtile.
// MODE 0: plain row-major C[m*N+n]
// MODE 1: scatter into g_qkv head-major layout
// ----------------------------------------------------------------------------
template <int MODE, int N, int K>
__global__ void __launch_bounds__(256)
sgemm_nt(const float* __restrict__ A, const float* __restrict__ B,
         const float* __restrict__ bias, float* __restrict__ C)
{
    __shared__ float As[16][128];
    __shared__ float Bs[16][128];

    const int m0 = blockIdx.y * 128;
    const int n0 = blockIdx.x * 128;
    const int tid = threadIdx.x;
    const int tx = tid & 15;        // output col group
    const int ty = tid >> 4;        // output row group

    // gmem tile loader indices: 2048 floats per operand tile = 2 x float4/thread
    const int lrow  = tid >> 2;       // 0..63
    const int lcol4 = (tid & 3) * 4;  // 0,4,8,12

    float acc[8][8];
#pragma unroll
    for (int i = 0; i < 8; i++)
#pragma unroll
        for (int j = 0; j < 8; j++) acc[i][j] = 0.f;

    for (int k0 = 0; k0 < K; k0 += 16) {
#pragma unroll
        for (int h = 0; h < 2; h++) {
            int r = lrow + 64 * h;
            float4 va = *(const float4*)&A[(size_t)(m0 + r) * K + k0 + lcol4];
            As[lcol4 + 0][r] = va.x; As[lcol4 + 1][r] = va.y;
            As[lcol4 + 2][r] = va.z; As[lcol4 + 3][r] = va.w;
            float4 vb = *(const float4*)&B[(size_t)(n0 + r) * K + k0 + lcol4];
            Bs[lcol4 + 0][r] = vb.x; Bs[lcol4 + 1][r] = vb.y;
            Bs[lcol4 + 2][r] = vb.z; Bs[lcol4 + 3][r] = vb.w;
        }
        __syncthreads();

#pragma unroll
        for (int kk = 0; kk < 16; kk++) {
            float a[8], b[8];
#pragma unroll
            for (int i = 0; i < 8; i++) a[i] = As[kk][ty + 16 * i];
#pragma unroll
            for (int j = 0; j < 8; j++) b[j] = Bs[kk][tx + 16 * j];
#pragma unroll
            for (int i = 0; i < 8; i++)
#pragma unroll
                for (int j = 0; j < 8; j++) acc[i][j] += a[i] * b[j];
        }
        __syncthreads();
    }

#pragma unroll
    for (int i = 0; i < 8; i++) {
        const int m = m0 + ty + 16 * i;
#pragma unroll
        for (int j = 0; j < 8; j++) {
            const int n = n0 + tx + 16 * j;
            const float v = acc[i][j] + bias[n];
            if (MODE == 0) {
                C[(size_t)m * N + n] = v;
            } else {
                const int which = n / DIM;
                const int rem   = n % DIM;      // h*64 + d
                g_qkv[(((size_t)which * NH + (rem >> 6)) * SEQ + m) * HD + (rem & 63)] = v;
            }
        }
    }
}

// ----------------------------------------------------------------------------
// Flash attention, fp32. One CTA = 64 queries x 1 head. 256 threads.
// Thread (ty=tid/16, tx=tid%16) owns rows {ty+16i} x cols {tx+16j}, i,j<4.
// smem stride 65 -> conflict-free K/V/P access patterns.
// ----------------------------------------------------------------------------
__global__ void __launch_bounds__(256)
flash_attn_kernel()
{
    extern __shared__ float sm[];
    float* Qs = sm;                  // 64*65
    float* Ks = Qs + 64 * 65;
    float* Vs = Ks + 64 * 65;
    float* Ps = Vs + 64 * 65;

    const int h  = blockIdx.y;
    const int q0 = blockIdx.x * 64;
    const int tid = threadIdx.x;
    const int tx = tid & 15;
    const int ty = tid >> 4;

    const float* Qg = g_qkv + ((size_t)(0 * NH + h) * SEQ) * HD;
    const float* Kg = g_qkv + ((size_t)(1 * NH + h) * SEQ) * HD;
    const float* Vg = g_qkv + ((size_t)(2 * NH + h) * SEQ) * HD;

    // Load Q tile, pre-scaled by 1/sqrt(hd) = 0.125
    const int lr = tid >> 2;          // row 0..63
    const int lc = (tid & 3) * 16;    // col base
#pragma unroll
    for (int q = 0; q < 4; q++) {
        float4 v = *(const float4*)&Qg[(size_t)(q0 + lr) * HD + lc + 4 * q];
        Qs[lr * 65 + lc + 4 * q + 0] = v.x * 0.125f;
        Qs[lr * 65 + lc + 4 * q + 1] = v.y * 0.125f;
        Qs[lr * 65 + lc + 4 * q + 2] = v.z * 0.125f;
        Qs[lr * 65 + lc + 4 * q + 3] = v.w * 0.125f;
    }

    float mrow[4], lrow_[4], acc[4][4];
#pragma unroll
    for (int i = 0; i < 4; i++) {
        mrow[i] = -1e30f; lrow_[i] = 0.f;
#pragma unroll
        for (int j = 0; j < 4; j++) acc[i][j] = 0.f;
    }

    for (int k0 = 0; k0 < SEQ; k0 += 64) {
        __syncthreads();   // prior iteration's Ks/Vs/Ps reads complete
#pragma unroll
        for (int q = 0; q < 4; q++) {
            float4 kv = *(const float4*)&Kg[(size_t)(k0 + lr) * HD + lc + 4 * q];
            Ks[lr * 65 + lc + 4 * q + 0] = kv.x;
            Ks[lr * 65 + lc + 4 * q + 1] = kv.y;
            Ks[lr * 65 + lc + 4 * q + 2] = kv.z;
            Ks[lr * 65 + lc + 4 * q + 3] = kv.w;
            float4 vv = *(const float4*)&Vg[(size_t)(k0 + lr) * HD + lc + 4 * q];
            Vs[lr * 65 + lc + 4 * q + 0] = vv.x;
            Vs[lr * 65 + lc + 4 * q + 1] = vv.y;
            Vs[lr * 65 + lc + 4 * q + 2] = vv.z;
            Vs[lr * 65 + lc + 4 * q + 3] = vv.w;
        }
        __syncthreads();

        // S = (Q/8) K^T
        float s[4][4];
#pragma unroll
        for (int i = 0; i < 4; i++)
#pragma unroll
            for (int j = 0; j < 4; j++) s[i][j] = 0.f;

#pragma unroll 16
        for (int d = 0; d < HD; d++) {
            float qv[4], kv[4];
#pragma unroll
            for (int i = 0; i < 4; i++) qv[i] = Qs[(ty + 16 * i) * 65 + d];
#pragma unroll
            for (int j = 0; j < 4; j++) kv[j] = Ks[(tx + 16 * j) * 65 + d];
#pragma unroll
            for (int i = 0; i < 4; i++)
#pragma unroll
                for (int j = 0; j < 4; j++) s[i][j] += qv[i] * kv[j];
        }

        // online softmax per row (reduce across the 16 tx lanes)
#pragma unroll
        for (int i = 0; i < 4; i++) {
            float mt = s[i][0];
#pragma unroll
            for (int j = 1; j < 4; j++) mt = fmaxf(mt, s[i][j]);
#pragma unroll
            for (int o = 8; o >= 1; o >>= 1)
                mt = fmaxf(mt, __shfl_xor_sync(0xffffffffu, mt, o));
            const float mn = fmaxf(mrow[i], mt);
            const float corr = __expf(mrow[i] - mn);
            mrow[i] = mn;
            float ls = 0.f;
#pragma unroll
            for (int j = 0; j < 4; j++) {
                s[i][j] = __expf(s[i][j] - mn);
                ls += s[i][j];
            }
#pragma unroll
            for (int o = 8; o >= 1; o >>= 1)
                ls += __shfl_xor_sync(0xffffffffu, ls, o);
            lrow_[i] = lrow_[i] * corr + ls;
#pragma unroll
            for (int j = 0; j < 4; j++) {
                acc[i][j] *= corr;
                Ps[(ty + 16 * i) * 65 + tx + 16 * j] = s[i][j];
            }
        }
        __syncthreads();

        // acc += P V
#pragma unroll 16
        for (int c = 0; c < 64; c++) {
            float pv[4], vv[4];
#pragma unroll
            for (int i = 0; i < 4; i++) pv[i] = Ps[(ty + 16 * i) * 65 + c];
#pragma unroll
            for (int j = 0; j < 4; j++) vv[j] = Vs[c * 65 + tx + 16 * j];
#pragma unroll
            for (int i = 0; i < 4; i++)
#pragma unroll
                for (int j = 0; j < 4; j++) acc[i][j] += pv[i] * vv[j];
        }
    }

    // normalize + store to g_attn [n][h*64+d]
#pragma unroll
    for (int i = 0; i < 4; i++) {
        const float inv = 1.f / lrow_[i];
        const int n = q0 + ty + 16 * i;
#pragma unroll
        for (int j = 0; j < 4; j++)
            g_attn[(size_t)n * DIM + h * HD + tx + 16 * j] = acc[i][j] * inv;
    }
}

// ----------------------------------------------------------------------------

extern "C" void kernel_launch(void* const* d_in, const int* in_sizes, int n_in,
                              void* d_out, int out_size)
{
    (void)in_sizes; (void)n_in; (void)out_size;
    const float* x     = (const float*)d_in[0];
    const float* w_qkv = (const float*)d_in[1];
    const float* b_qkv = (const float*)d_in[2];
    const float* w_out = (const float*)d_in[3];
    const float* b_out = (const float*)d_in[4];
    float* out = (float*)d_out;

    float* attn_ptr = nullptr;
    cudaGetSymbolAddress((void**)&attn_ptr, g_attn);

    // 1) QKV projection, scattered into head-major layout
    {
        dim3 grid(3 * DIM / 128, SEQ / 128);   // (18, 32)
        sgemm_nt<1, 3 * DIM, DIM><<<grid, 256>>>(x, w_qkv, b_qkv, nullptr);
    }

    // 2) flash attention
    {
        const int smem = 4 * 64 * 65 * (int)sizeof(float);  // 66560 B
        cudaFuncSetAttribute(flash_attn_kernel,
                             cudaFuncAttributeMaxDynamicSharedMemorySize, smem);
        dim3 grid(SEQ / 64, NH);               // (64, 12)
        flash_attn_kernel<<<grid, 256, smem>>>();
    }

    // 3) output projection
    {
        dim3 grid(DIM / 128, SEQ / 128);       // (6, 32)
        sgemm_nt<0, DIM, DIM><<<grid, 256>>>(attn_ptr, w_out, b_out, out);
    }
}

// round 2
// speedup vs baseline: 2.7172x; 2.7172x over previous
#include <cuda_runtime.h>
#include <cuda_bf16.h>

#define SEQ 4096
#define DIM 768
#define NH  12
#define HD  64

typedef __nv_bfloat16  bf16;
typedef __nv_bfloat162 bf162;

// ---------------- scratch (static device arrays; no allocation) ----------------
__device__ bf16 g_xh [SEQ * DIM],      g_xl [SEQ * DIM];
__device__ bf16 g_wqh[3 * DIM * DIM],  g_wql[3 * DIM * DIM];
__device__ bf16 g_woh[DIM * DIM],      g_wol[DIM * DIM];
__device__ bf16 g_qkvh[3 * NH * SEQ * HD], g_qkvl[3 * NH * SEQ * HD];
__device__ bf16 g_ah [SEQ * DIM],      g_al [SEQ * DIM];

// ---------------- helpers ----------------
__device__ __forceinline__ void mma_bf16(float d[4], const unsigned a[4],
                                         unsigned b0, unsigned b1) {
    asm volatile(
        "mma.sync.aligned.m16n8k16.row.col.f32.bf16.bf16.f32 "
        "{%0,%1,%2,%3}, {%4,%5,%6,%7}, {%8,%9}, {%0,%1,%2,%3};\n"
        : "+f"(d[0]), "+f"(d[1]), "+f"(d[2]), "+f"(d[3])
        : "r"(a[0]), "r"(a[1]), "r"(a[2]), "r"(a[3]), "r"(b0), "r"(b1));
}

// pack two fp32 -> bf16x2 (lo = a, hi = b)
__device__ __forceinline__ unsigned packf(float a, float b) {
    bf162 t = __floats2bfloat162_rn(a, b);
    return *reinterpret_cast<unsigned*>(&t);
}
__device__ __forceinline__ unsigned packh(bf16 a, bf16 b) {
    bf162 t = __halves2bfloat162(a, b);
    return *reinterpret_cast<unsigned*>(&t);
}
__device__ __forceinline__ float lo_f(unsigned u) { return __uint_as_float(u << 16); }
__device__ __forceinline__ float hi_f(unsigned u) { return __uint_as_float(u & 0xffff0000u); }

// fast e^x on the FMA pipe (no MUFU). |rel err| ~2e-6, valid for x <= ~1.
__device__ __forceinline__ float fexp(float x) {
    x = fmaxf(x, -80.f);
    float y = fmaf(x, 1.4426950408889634f, 12582912.f);
    float i = y - 12582912.f;                       // round(x*log2e)
    float f = fmaf(x, 1.4426950408889634f, -i);     // frac in [-0.5,0.5]
    float p = 1.33335581e-3f;
    p = fmaf(p, f, 9.61804886e-3f);
    p = fmaf(p, f, 5.55041086e-2f);
    p = fmaf(p, f, 2.40226507e-1f);
    p = fmaf(p, f, 6.93147182e-1f);
    p = fmaf(p, f, 1.0f);
    return p * __uint_as_float((unsigned)(((int)i + 127)) << 23);
}

// ---------------- fp32 -> bf16 hi/lo split ----------------
__global__ void split_kernel(const float* __restrict__ src,
                             bf16* __restrict__ h, bf16* __restrict__ l, int n) {
    int i = blockIdx.x * 256 + threadIdx.x;
    if (i < n) {
        float v  = src[i];
        bf16 hi = __float2bfloat16_rn(v);
        h[i] = hi;
        l[i] = __float2bfloat16_rn(v - __bfloat162float(hi));
    }
}

// ---------------- GEMM (NT) with split-bf16 x3: C = A B^T + bias ----------------
// BM=BN=128, BK=32, 256 threads, warp grid 4(m) x 2(n), warp tile 32x64.
// MODE 0: fp32 C row-major.  MODE 1: scatter into g_qkv head-major bf16 hi/lo.
template <int MODE, int N, int K>
__global__ void __launch_bounds__(256)
gemm_bf16x3(const bf16* __restrict__ Agh, const bf16* __restrict__ Agl,
            const bf16* __restrict__ Bgh, const bf16* __restrict__ Bgl,
            const float* __restrict__ bias, float* __restrict__ C)
{
    __shared__ bf16 Ah[128][40], Al[128][40], Bh[128][40], Bl[128][40];

    const int tid = threadIdx.x, lane = tid & 31, warp = tid >> 5;
    const int wm = warp >> 1, wn = warp & 1;
    const int m0 = blockIdx.y * 128, n0 = blockIdx.x * 128;

    float acc[2][8][4];
#pragma unroll
    for (int mt = 0; mt < 2; mt++)
#pragma unroll
        for (int nt = 0; nt < 8; nt++)
#pragma unroll
            for (int e = 0; e < 4; e++) acc[mt][nt][e] = 0.f;

    for (int k0 = 0; k0 < K; k0 += 32) {
        __syncthreads();
#pragma unroll
        for (int i = 0; i < 2; i++) {
            int c = tid + 256 * i;
            int row = c >> 2, col8 = (c & 3) * 8;
            *(uint4*)&Ah[row][col8] = *(const uint4*)&Agh[(size_t)(m0 + row) * K + k0 + col8];
            *(uint4*)&Al[row][col8] = *(const uint4*)&Agl[(size_t)(m0 + row) * K + k0 + col8];
            *(uint4*)&Bh[row][col8] = *(const uint4*)&Bgh[(size_t)(n0 + row) * K + k0 + col8];
            *(uint4*)&Bl[row][col8] = *(const uint4*)&Bgl[(size_t)(n0 + row) * K + k0 + col8];
        }
        __syncthreads();

#pragma unroll
        for (int kk = 0; kk < 2; kk++) {
            const int c0 = kk * 16 + (lane & 3) * 2;
            unsigned ah[2][4], al_[2][4], bh[8][2], bl_[8][2];
#pragma unroll
            for (int mt = 0; mt < 2; mt++) {
                int r = wm * 32 + mt * 16 + (lane >> 2);
                ah[mt][0]  = *(unsigned*)&Ah[r][c0];
                ah[mt][1]  = *(unsigned*)&Ah[r + 8][c0];
                ah[mt][2]  = *(unsigned*)&Ah[r][c0 + 8];
                ah[mt][3]  = *(unsigned*)&Ah[r + 8][c0 + 8];
                al_[mt][0] = *(unsigned*)&Al[r][c0];
                al_[mt][1] = *(unsigned*)&Al[r + 8][c0];
                al_[mt][2] = *(unsigned*)&Al[r][c0 + 8];
                al_[mt][3] = *(unsigned*)&Al[r + 8][c0 + 8];
            }
#pragma unroll
            for (int nt = 0; nt < 8; nt++) {
                int n = wn * 64 + nt * 8 + (lane >> 2);
                bh[nt][0]  = *(unsigned*)&Bh[n][c0];
                bh[nt][1]  = *(unsigned*)&Bh[n][c0 + 8];
                bl_[nt][0] = *(unsigned*)&Bl[n][c0];
                bl_[nt][1] = *(unsigned*)&Bl[n][c0 + 8];
            }
#pragma unroll
            for (int mt = 0; mt < 2; mt++)
#pragma unroll
                for (int nt = 0; nt < 8; nt++) {
                    mma_bf16(acc[mt][nt], ah[mt],  bh[nt][0],  bh[nt][1]);
                    mma_bf16(acc[mt][nt], ah[mt],  bl_[nt][0], bl_[nt][1]);
                    mma_bf16(acc[mt][nt], al_[mt], bh[nt][0],  bh[nt][1]);
                }
        }
    }

    // epilogue
#pragma unroll
    for (int mt = 0; mt < 2; mt++) {
        const int m = m0 + wm * 32 + mt * 16 + (lane >> 2);
#pragma unroll
        for (int nt = 0; nt < 8; nt++) {
            const int n = n0 + wn * 64 + nt * 8 + (lane & 3) * 2;
            const float b0 = bias[n], b1 = bias[n + 1];
            float v[4];
            v[0] = acc[mt][nt][0] + b0; v[1] = acc[mt][nt][1] + b1;
            v[2] = acc[mt][nt][2] + b0; v[3] = acc[mt][nt][3] + b1;
            if (MODE == 0) {
                C[(size_t)m * N + n]           = v[0];
                C[(size_t)m * N + n + 1]       = v[1];
                C[(size_t)(m + 8) * N + n]     = v[2];
                C[(size_t)(m + 8) * N + n + 1] = v[3];
            } else {
#pragma unroll
                for (int e = 0; e < 4; e++) {
                    const int mm = m + ((e >> 1) & 1) * 8;
                    const int nn = n + (e & 1);
                    const int which = nn / DIM;
                    const int rem   = nn - which * DIM;   // h*64+d
                    const size_t idx =
                        (((size_t)which * NH + (rem >> 6)) * SEQ + mm) * HD + (rem & 63);
                    bf16 hi = __float2bfloat16_rn(v[e]);
                    g_qkvh[idx] = hi;
                    g_qkvl[idx] = __float2bfloat16_rn(v[e] - __bfloat162float(hi));
                }
            }
        }
    }
}

// ---------------- Flash attention, split-bf16 mma + FMA-pipe softmax ----------------
// CTA: 128 queries x 1 head, 256 threads (8 warps, 16 query rows each).
__global__ void __launch_bounds__(256)
flash_mma()
{
    extern __shared__ char smraw[];
    bf16* Qh = (bf16*)smraw;            // [128][72]
    bf16* Ql = Qh + 128 * 72;
    bf16* Kh = Ql + 128 * 72;           // [64][72]   (key, d)
    bf16* Kl = Kh + 64 * 72;
    bf16* Vh = Kl + 64 * 72;            // [64][72]   transposed (d, key)
    bf16* Vl = Vh + 64 * 72;

    const int h  = blockIdx.y;
    const int q0 = blockIdx.x * 128;
    const int tid = threadIdx.x, lane = tid & 31, w = tid >> 5;

    const bf16* Qg_h = g_qkvh + ((size_t)(0 * NH + h) * SEQ + q0) * HD;
    const bf16* Qg_l = g_qkvl + ((size_t)(0 * NH + h) * SEQ + q0) * HD;
    const bf16* Kg_h = g_qkvh + (size_t)(NH + h) * SEQ * HD;
    const bf16* Kg_l = g_qkvl + (size_t)(NH + h) * SEQ * HD;
    const bf16* Vg_h = g_qkvh + (size_t)(2 * NH + h) * SEQ * HD;
    const bf16* Vg_l = g_qkvl + (size_t)(2 * NH + h) * SEQ * HD;

    // Q -> smem, pre-scaled by 1/8 (exact in bf16)
    const bf162 sc = __floats2bfloat162_rn(0.125f, 0.125f);
#pragma unroll
    for (int i = 0; i < 4; i++) {
        int c = tid + 256 * i;
        int row = c >> 3, col8 = (c & 7) * 8;
        uint4 vh = *(const uint4*)&Qg_h[row * 64 + col8];
        uint4 vl = *(const uint4*)&Qg_l[row * 64 + col8];
        bf162* ph = (bf162*)&vh;
        bf162* pl = (bf162*)&vl;
#pragma unroll
        for (int e = 0; e < 4; e++) { ph[e] = __hmul2(ph[e], sc); pl[e] = __hmul2(pl[e], sc); }
        *(uint4*)&Qh[row * 72 + col8] = vh;
        *(uint4*)&Ql[row * 72 + col8] = vl;
    }
    __syncthreads();

    // Q fragments -> registers (persist across all key tiles)
    unsigned qfh[4][4], qfl[4][4];
    {
        const int r = w * 16 + (lane >> 2);
#pragma unroll
        for (int kk = 0; kk < 4; kk++) {
            const int c0 = kk * 16 + (lane & 3) * 2;
            qfh[kk][0] = *(unsigned*)&Qh[r * 72 + c0];
            qfh[kk][1] = *(unsigned*)&Qh[(r + 8) * 72 + c0];
            qfh[kk][2] = *(unsigned*)&Qh[r * 72 + c0 + 8];
            qfh[kk][3] = *(unsigned*)&Qh[(r + 8) * 72 + c0 + 8];
            qfl[kk][0] = *(unsigned*)&Ql[r * 72 + c0];
            qfl[kk][1] = *(unsigned*)&Ql[(r + 8) * 72 + c0];
            qfl[kk][2] = *(unsigned*)&Ql[r * 72 + c0 + 8];
            qfl[kk][3] = *(unsigned*)&Ql[(r + 8) * 72 + c0 + 8];
        }
    }

    float o[8][4];
#pragma unroll
    for (int nt = 0; nt < 8; nt++)
#pragma unroll
        for (int e = 0; e < 4; e++) o[nt][e] = 0.f;
    float m0r = -1e30f, m1r = -1e30f, l0 = 0.f, l1 = 0.f;

    for (int kt = 0; kt < SEQ / 64; kt++) {
        __syncthreads();   // previous tile fully consumed
        // K tile copy
#pragma unroll
        for (int i = 0; i < 2; i++) {
            int c = tid + 256 * i;
            int row = c >> 3, col8 = (c & 7) * 8;
            *(uint4*)&Kh[row * 72 + col8] =
                *(const uint4*)&Kg_h[(size_t)(kt * 64 + row) * 64 + col8];
            *(uint4*)&Kl[row * 72 + col8] =
                *(const uint4*)&Kg_l[(size_t)(kt * 64 + row) * 64 + col8];
        }
        // V tile transpose: (key,d) -> (d,key), pair keys into bf16x2
        {
            const int kp = tid >> 3, dg = tid & 7;
            uint4 r0h = *(const uint4*)&Vg_h[(size_t)(kt * 64 + 2 * kp) * 64 + dg * 8];
            uint4 r1h = *(const uint4*)&Vg_h[(size_t)(kt * 64 + 2 * kp + 1) * 64 + dg * 8];
            uint4 r0l = *(const uint4*)&Vg_l[(size_t)(kt * 64 + 2 * kp) * 64 + dg * 8];
            uint4 r1l = *(const uint4*)&Vg_l[(size_t)(kt * 64 + 2 * kp + 1) * 64 + dg * 8];
            const bf16* a0 = (const bf16*)&r0h;
            const bf16* a1 = (const bf16*)&r1h;
            const bf16* b0 = (const bf16*)&r0l;
            const bf16* b1 = (const bf16*)&r1l;
#pragma unroll
            for (int e0 = 0; e0 < 8; e0++) {
                const int e = (e0 + dg) & 7;       // bank-rotation on store order
                const int d = dg * 8 + e;
                *(unsigned*)&Vh[d * 72 + 2 * kp] = packh(a0[e], a1[e]);
                *(unsigned*)&Vl[d * 72 + 2 * kp] = packh(b0[e], b1[e]);
            }
        }
        __syncthreads();

        // S = (Q/8) K^T
        float s[8][4];
#pragma unroll
        for (int nt = 0; nt < 8; nt++)
#pragma unroll
            for (int e = 0; e < 4; e++) s[nt][e] = 0.f;
#pragma unroll
        for (int kk = 0; kk < 4; kk++) {
            const int c0 = kk * 16 + (lane & 3) * 2;
#pragma unroll
            for (int nt = 0; nt < 8; nt++) {
                const int n = nt * 8 + (lane >> 2);
                unsigned b0h = *(unsigned*)&Kh[n * 72 + c0];
                unsigned b1h = *(unsigned*)&Kh[n * 72 + c0 + 8];
                unsigned b0l = *(unsigned*)&Kl[n * 72 + c0];
                unsigned b1l = *(unsigned*)&Kl[n * 72 + c0 + 8];
                mma_bf16(s[nt], qfh[kk], b0h, b1h);
                mma_bf16(s[nt], qfh[kk], b0l, b1l);
                mma_bf16(s[nt], qfl[kk], b0h, b1h);
            }
        }

        // online softmax (rows r=lane/4 and r+8); reduce across lane%4
        float tm0 = -1e30f, tm1 = -1e30f;
#pragma unroll
        for (int nt = 0; nt < 8; nt++) {
            tm0 = fmaxf(tm0, fmaxf(s[nt][0], s[nt][1]));
            tm1 = fmaxf(tm1, fmaxf(s[nt][2], s[nt][3]));
        }
        tm0 = fmaxf(tm0, __shfl_xor_sync(0xffffffffu, tm0, 1));
        tm0 = fmaxf(tm0, __shfl_xor_sync(0xffffffffu, tm0, 2));
        tm1 = fmaxf(tm1, __shfl_xor_sync(0xffffffffu, tm1, 1));
        tm1 = fmaxf(tm1, __shfl_xor_sync(0xffffffffu, tm1, 2));
        const float mn0 = fmaxf(m0r, tm0), mn1 = fmaxf(m1r, tm1);
        const float c0f = fexp(m0r - mn0), c1f = fexp(m1r - mn1);
        m0r = mn0; m1r = mn1;
        float ls0 = 0.f, ls1 = 0.f;
#pragma unroll
        for (int nt = 0; nt < 8; nt++) {
            s[nt][0] = fexp(s[nt][0] - mn0); ls0 += s[nt][0];
            s[nt][1] = fexp(s[nt][1] - mn0); ls0 += s[nt][1];
            s[nt][2] = fexp(s[nt][2] - mn1); ls1 += s[nt][2];
            s[nt][3] = fexp(s[nt][3] - mn1); ls1 += s[nt][3];
        }
        ls0 += __shfl_xor_sync(0xffffffffu, ls0, 1);
        ls0 += __shfl_xor_sync(0xffffffffu, ls0, 2);
        ls1 += __shfl_xor_sync(0xffffffffu, ls1, 1);
        ls1 += __shfl_xor_sync(0xffffffffu, ls1, 2);
        l0 = l0 * c0f + ls0;
        l1 = l1 * c1f + ls1;
#pragma unroll
        for (int nt = 0; nt < 8; nt++) {
            o[nt][0] *= c0f; o[nt][1] *= c0f; o[nt][2] *= c1f; o[nt][3] *= c1f;
        }

        // O += P V  (P fragments built directly from S accumulators)
#pragma unroll
        for (int kk = 0; kk < 4; kk++) {
            const int t0 = 2 * kk, t1 = 2 * kk + 1;
            unsigned pa[4], pl[4];
            pa[0] = packf(s[t0][0], s[t0][1]);
            pa[1] = packf(s[t0][2], s[t0][3]);
            pa[2] = packf(s[t1][0], s[t1][1]);
            pa[3] = packf(s[t1][2], s[t1][3]);
            pl[0] = packf(s[t0][0] - lo_f(pa[0]), s[t0][1] - hi_f(pa[0]));
            pl[1] = packf(s[t0][2] - lo_f(pa[1]), s[t0][3] - hi_f(pa[1]));
            pl[2] = packf(s[t1][0] - lo_f(pa[2]), s[t1][1] - hi_f(pa[2]));
            pl[3] = packf(s[t1][2] - lo_f(pa[3]), s[t1][3] - hi_f(pa[3]));
            const int c0 = kk * 16 + (lane & 3) * 2;
#pragma unroll
            for (int nt = 0; nt < 8; nt++) {
                const int n = nt * 8 + (lane >> 2);
                unsigned b0h = *(unsigned*)&Vh[n * 72 + c0];
                unsigned b1h = *(unsigned*)&Vh[n * 72 + c0 + 8];
                unsigned b0l = *(unsigned*)&Vl[n * 72 + c0];
                unsigned b1l = *(unsigned*)&Vl[n * 72 + c0 + 8];
                mma_bf16(o[nt], pa, b0h, b1h);
                mma_bf16(o[nt], pa, b0l, b1l);
                mma_bf16(o[nt], pl, b0h, b1h);
            }
        }
    }

    // normalize + store split bf16 into [n][h*64+d]
    const float inv0 = 1.f / l0, inv1 = 1.f / l1;
    const int r = q0 + w * 16 + (lane >> 2);
#pragma unroll
    for (int nt = 0; nt < 8; nt++) {
        const int col = h * 64 + nt * 8 + (lane & 3) * 2;
        {
            float a = o[nt][0] * inv0, b = o[nt][1] * inv0;
            bf16 ha = __float2bfloat16_rn(a), hb = __float2bfloat16_rn(b);
            *(unsigned*)&g_ah[(size_t)r * DIM + col] = packh(ha, hb);
            *(unsigned*)&g_al[(size_t)r * DIM + col] =
                packf(a - __bfloat162float(ha), b - __bfloat162float(hb));
        }
        {
            float a = o[nt][2] * inv1, b = o[nt][3] * inv1;
            bf16 ha = __float2bfloat16_rn(a), hb = __float2bfloat16_rn(b);
            *(unsigned*)&g_ah[(size_t)(r + 8) * DIM + col] = packh(ha, hb);
            *(unsigned*)&g_al[(size_t)(r + 8) * DIM + col] =
                packf(a - __bfloat162float(ha), b - __bfloat162float(hb));
        }
    }
}

// ----------------------------------------------------------------------------
extern "C" void kernel_launch(void* const* d_in, const int* in_sizes, int n_in,
                              void* d_out, int out_size)
{
    (void)in_sizes; (void)n_in; (void)out_size;
    const float* x     = (const float*)d_in[0];
    const float* w_qkv = (const float*)d_in[1];
    const float* b_qkv = (const float*)d_in[2];
    const float* w_out = (const float*)d_in[3];
    const float* b_out = (const float*)d_in[4];
    float* out = (float*)d_out;

    bf16 *xh, *xl, *wqh, *wql, *woh, *wol, *ah, *al;
    cudaGetSymbolAddress((void**)&xh,  g_xh);  cudaGetSymbolAddress((void**)&xl,  g_xl);
    cudaGetSymbolAddress((void**)&wqh, g_wqh); cudaGetSymbolAddress((void**)&wql, g_wql);
    cudaGetSymbolAddress((void**)&woh, g_woh); cudaGetSymbolAddress((void**)&wol, g_wol);
    cudaGetSymbolAddress((void**)&ah,  g_ah);  cudaGetSymbolAddress((void**)&al,  g_al);

    // 0) fp32 -> split bf16
    split_kernel<<<(SEQ * DIM + 255) / 256, 256>>>(x, xh, xl, SEQ * DIM);
    split_kernel<<<(3 * DIM * DIM + 255) / 256, 256>>>(w_qkv, wqh, wql, 3 * DIM * DIM);
    split_kernel<<<(DIM * DIM + 255) / 256, 256>>>(w_out, woh, wol, DIM * DIM);

    // 1) QKV projection -> head-major split-bf16 qkv
    {
        dim3 grid(3 * DIM / 128, SEQ / 128);   // (18, 32)
        gemm_bf16x3<1, 3 * DIM, DIM><<<grid, 256>>>(xh, xl, wqh, wql, b_qkv, nullptr);
    }

    // 2) flash attention
    {
        const int smem = (2 * 128 * 72 + 4 * 64 * 72) * (int)sizeof(bf16); // 73728
        cudaFuncSetAttribute(flash_mma,
                             cudaFuncAttributeMaxDynamicSharedMemorySize, smem);
        dim3 grid(SEQ / 128, NH);              // (32, 12)
        flash_mma<<<grid, 256, smem>>>();
    }

    // 3) output projection
    {
        dim3 grid(DIM / 128, SEQ / 128);       // (6, 32)
        gemm_bf16x3<0, DIM, DIM><<<grid, 256>>>(ah, al, woh, wol, b_out, out);
    }
}

// round 5
// speedup vs baseline: 3.1111x; 1.1450x over previous
#include <cuda_runtime.h>
#include <cuda_bf16.h>

#define SEQ 4096
#define DIM 768
#define NH  12
#define HD  64

typedef __nv_bfloat16  bf16;
typedef __nv_bfloat162 bf162;

// ---------------- scratch (static device arrays; no allocation) ----------------
__device__ bf16 g_xh [SEQ * DIM],      g_xl [SEQ * DIM];
__device__ bf16 g_wqh[3 * DIM * DIM],  g_wql[3 * DIM * DIM];
__device__ bf16 g_woh[DIM * DIM],      g_wol[DIM * DIM];
__device__ bf16 g_qkvh[2 * NH * SEQ * HD], g_qkvl[2 * NH * SEQ * HD]; // Q,K head-major
__device__ bf16 g_vth[NH * HD * SEQ],  g_vtl[NH * HD * SEQ];          // V transposed [h][d][key]
__device__ bf16 g_ah [SEQ * DIM],      g_al [SEQ * DIM];

// ---------------- helpers ----------------
__device__ __forceinline__ void mma_bf16(float d[4], const unsigned a[4],
                                         unsigned b0, unsigned b1) {
    asm volatile(
        "mma.sync.aligned.m16n8k16.row.col.f32.bf16.bf16.f32 "
        "{%0,%1,%2,%3}, {%4,%5,%6,%7}, {%8,%9}, {%0,%1,%2,%3};\n"
        : "+f"(d[0]), "+f"(d[1]), "+f"(d[2]), "+f"(d[3])
        : "r"(a[0]), "r"(a[1]), "r"(a[2]), "r"(a[3]), "r"(b0), "r"(b1));
}

__device__ __forceinline__ void cpa16(void* s, const void* g) {
    unsigned sa = (unsigned)__cvta_generic_to_shared(s);
    asm volatile("cp.async.cg.shared.global [%0], [%1], 16;" :: "r"(sa), "l"(g));
}
__device__ __forceinline__ void cpa_commit() { asm volatile("cp.async.commit_group;"); }
template <int Npend>
__device__ __forceinline__ void cpa_wait() { asm volatile("cp.async.wait_group %0;" :: "n"(Npend)); }

__device__ __forceinline__ unsigned packf(float a, float b) {
    bf162 t = __floats2bfloat162_rn(a, b);
    return *reinterpret_cast<unsigned*>(&t);
}
__device__ __forceinline__ float lo_f(unsigned u) { return __uint_as_float(u << 16); }
__device__ __forceinline__ float hi_f(unsigned u) { return __uint_as_float(u & 0xffff0000u); }

// fast e^x on the FMA pipe (no MUFU). |rel err| ~2e-6, valid for x <= ~1.
__device__ __forceinline__ float fexp(float x) {
    x = fmaxf(x, -80.f);
    float y = fmaf(x, 1.4426950408889634f, 12582912.f);
    float i = y - 12582912.f;
    float f = fmaf(x, 1.4426950408889634f, -i);
    float p = 1.33335581e-3f;
    p = fmaf(p, f, 9.61804886e-3f);
    p = fmaf(p, f, 5.55041086e-2f);
    p = fmaf(p, f, 2.40226507e-1f);
    p = fmaf(p, f, 6.93147182e-1f);
    p = fmaf(p, f, 1.0f);
    return p * __uint_as_float((unsigned)(((int)i + 127)) << 23);
}

// ---------------- fp32 -> bf16 hi/lo split ----------------
__global__ void split_kernel(const float* __restrict__ src,
                             bf16* __restrict__ h, bf16* __restrict__ l, int n) {
    int i = blockIdx.x * 256 + threadIdx.x;
    if (i < n) {
        float v  = src[i];
        bf16 hi = __float2bfloat16_rn(v);
        h[i] = hi;
        l[i] = __float2bfloat16_rn(v - __bfloat162float(hi));
    }
}

// ---------------- GEMM (NT), split-bf16 x3, cp.async double-buffered ----------------
// BM=BN=128, BK=32, 256 threads, warps 4(m) x 2(n), warp tile 32x64.
// MODE 0: fp32 C.  MODE 1: Q,K -> g_qkv head-major; V -> g_vt transposed.
template <int MODE, int N, int K>
__global__ void __launch_bounds__(256)
gemm_bf16x3(const bf16* __restrict__ Agh, const bf16* __restrict__ Agl,
            const bf16* __restrict__ Bgh, const bf16* __restrict__ Bgl,
            const float* __restrict__ bias, float* __restrict__ C)
{
    extern __shared__ bf16 smg[];
    const int TS = 128 * 40;

    const int tid = threadIdx.x, lane = tid & 31, warp = tid >> 5;
    const int wm = warp >> 1, wn = warp & 1;
    const int m0 = blockIdx.y * 128, n0 = blockIdx.x * 128;

    float acc[2][8][4];
#pragma unroll
    for (int mt = 0; mt < 2; mt++)
#pragma unroll
        for (int nt = 0; nt < 8; nt++)
#pragma unroll
            for (int e = 0; e < 4; e++) acc[mt][nt][e] = 0.f;

    const int lrow  = tid >> 2;        // 0..63
    const int lcol8 = (tid & 3) * 8;   // 0,8,16,24

#define GEMM_ISSUE(K0, S)                                                          \
    {                                                                              \
        bf16* b = smg + (S) * 4 * TS;                                              \
        _Pragma("unroll")                                                          \
        for (int i_ = 0; i_ < 2; i_++) {                                           \
            int row = lrow + 64 * i_;                                              \
            cpa16(b + row * 40 + lcol8,                                            \
                  Agh + (size_t)(m0 + row) * K + (K0) + lcol8);                    \
            cpa16(b + TS + row * 40 + lcol8,                                       \
                  Agl + (size_t)(m0 + row) * K + (K0) + lcol8);                    \
            cpa16(b + 2 * TS + row * 40 + lcol8,                                   \
                  Bgh + (size_t)(n0 + row) * K + (K0) + lcol8);                    \
            cpa16(b + 3 * TS + row * 40 + lcol8,                                   \
                  Bgl + (size_t)(n0 + row) * K + (K0) + lcol8);                    \
        }                                                                          \
        cpa_commit();                                                              \
    }

    GEMM_ISSUE(0, 0);

    const int KT = K / 32;
    for (int kt = 0; kt < KT; kt++) {
        if (kt + 1 < KT) { GEMM_ISSUE((kt + 1) * 32, (kt + 1) & 1); cpa_wait<1>(); }
        else             { cpa_wait<0>(); }
        __syncthreads();

        const bf16* As_h = smg + (kt & 1) * 4 * TS;
        const bf16* As_l = As_h + TS;
        const bf16* Bs_h = As_h + 2 * TS;
        const bf16* Bs_l = As_h + 3 * TS;

#pragma unroll
        for (int kk = 0; kk < 2; kk++) {
            const int c0 = kk * 16 + (lane & 3) * 2;
            unsigned ah[2][4], al_[2][4], bh[8][2], bl_[8][2];
#pragma unroll
            for (int mt = 0; mt < 2; mt++) {
                int r = wm * 32 + mt * 16 + (lane >> 2);
                ah[mt][0]  = *(const unsigned*)&As_h[r * 40 + c0];
                ah[mt][1]  = *(const unsigned*)&As_h[(r + 8) * 40 + c0];
                ah[mt][2]  = *(const unsigned*)&As_h[r * 40 + c0 + 8];
                ah[mt][3]  = *(const unsigned*)&As_h[(r + 8) * 40 + c0 + 8];
                al_[mt][0] = *(const unsigned*)&As_l[r * 40 + c0];
                al_[mt][1] = *(const unsigned*)&As_l[(r + 8) * 40 + c0];
                al_[mt][2] = *(const unsigned*)&As_l[r * 40 + c0 + 8];
                al_[mt][3] = *(const unsigned*)&As_l[(r + 8) * 40 + c0 + 8];
            }
#pragma unroll
            for (int nt = 0; nt < 8; nt++) {
                int n = wn * 64 + nt * 8 + (lane >> 2);
                bh[nt][0]  = *(const unsigned*)&Bs_h[n * 40 + c0];
                bh[nt][1]  = *(const unsigned*)&Bs_h[n * 40 + c0 + 8];
                bl_[nt][0] = *(const unsigned*)&Bs_l[n * 40 + c0];
                bl_[nt][1] = *(const unsigned*)&Bs_l[n * 40 + c0 + 8];
            }
#pragma unroll
            for (int mt = 0; mt < 2; mt++)
#pragma unroll
                for (int nt = 0; nt < 8; nt++) {
                    mma_bf16(acc[mt][nt], ah[mt],  bh[nt][0],  bh[nt][1]);
                    mma_bf16(acc[mt][nt], ah[mt],  bl_[nt][0], bl_[nt][1]);
                    mma_bf16(acc[mt][nt], al_[mt], bh[nt][0],  bh[nt][1]);
                }
        }
        __syncthreads();
    }

    // epilogue
#pragma unroll
    for (int mt = 0; mt < 2; mt++) {
        const int m = m0 + wm * 32 + mt * 16 + (lane >> 2);
#pragma unroll
        for (int nt = 0; nt < 8; nt++) {
            const int n = n0 + wn * 64 + nt * 8 + (lane & 3) * 2;
            const float b0 = bias[n], b1 = bias[n + 1];
            float v[4];
            v[0] = acc[mt][nt][0] + b0; v[1] = acc[mt][nt][1] + b1;
            v[2] = acc[mt][nt][2] + b0; v[3] = acc[mt][nt][3] + b1;
            if (MODE == 0) {
                C[(size_t)m * N + n]           = v[0];
                C[(size_t)m * N + n + 1]       = v[1];
                C[(size_t)(m + 8) * N + n]     = v[2];
                C[(size_t)(m + 8) * N + n + 1] = v[3];
            } else {
#pragma unroll
                for (int e = 0; e < 4; e++) {
                    const int mm = m + ((e >> 1) & 1) * 8;
                    const int nn = n + (e & 1);
                    const int which = nn / DIM;
                    const int rem   = nn - which * DIM;   // h*64+d
                    bf16 hi = __float2bfloat16_rn(v[e]);
                    bf16 lo = __float2bfloat16_rn(v[e] - __bfloat162float(hi));
                    if (which == 2) {                     // V: transposed [h*64+d][key]
                        const size_t idx = (size_t)rem * SEQ + mm;
                        g_vth[idx] = hi; g_vtl[idx] = lo;
                    } else {                              // Q,K: [which][h][n][d]
                        const size_t idx =
                            (((size_t)which * NH + (rem >> 6)) * SEQ + mm) * HD + (rem & 63);
                        g_qkvh[idx] = hi; g_qkvl[idx] = lo;
                    }
                }
            }
        }
    }
#undef GEMM_ISSUE
}

// ---------------- Flash attention: mma + cp.async double-buffered K/V ----------------
// CTA: 128 queries x 1 head, 256 threads (8 warps, 16 query rows each).
__global__ void __launch_bounds__(256)
flash_mma()
{
    extern __shared__ char smraw[];
    bf16* Qh   = (bf16*)smraw;              // [128][72]
    bf16* Ql   = Qh + 128 * 72;
    bf16* Kbuf = Ql + 128 * 72;             // [2 stages][Kh|Kl][64*72]
    bf16* Vbuf = Kbuf + 2 * 2 * 64 * 72;    // [2 stages][Vth|Vtl][64*72]  (d, key)
    const int KTS = 64 * 72;

    const int h  = blockIdx.y;
    const int q0 = blockIdx.x * 128;
    const int tid = threadIdx.x, lane = tid & 31, w = tid >> 5;

    const bf16* Qg_h = g_qkvh + ((size_t)(0 * NH + h) * SEQ + q0) * HD;
    const bf16* Qg_l = g_qkvl + ((size_t)(0 * NH + h) * SEQ + q0) * HD;
    const bf16* Kg_h = g_qkvh + (size_t)(NH + h) * SEQ * HD;
    const bf16* Kg_l = g_qkvl + (size_t)(NH + h) * SEQ * HD;
    const bf16* Vg_h = g_vth + (size_t)h * HD * SEQ;   // [d][key]
    const bf16* Vg_l = g_vtl + (size_t)h * HD * SEQ;

    // 64x64 tile = 512 16B chunks; 256 threads -> 2 chunks per thread per array
    const int frow  = tid >> 3;        // 0..31
    const int fcol8 = (tid & 7) * 8;   // 0..56

#define FLASH_ISSUE(KT_, S)                                                        \
    {                                                                              \
        bf16* kb = Kbuf + (S) * 2 * KTS;                                           \
        bf16* vb = Vbuf + (S) * 2 * KTS;                                           \
        _Pragma("unroll")                                                          \
        for (int i_ = 0; i_ < 2; i_++) {                                           \
            int row = frow + 32 * i_;                                              \
            cpa16(kb + row * 72 + fcol8,                                           \
                  Kg_h + (size_t)((KT_) * 64 + row) * 64 + fcol8);                 \
            cpa16(kb + KTS + row * 72 + fcol8,                                     \
                  Kg_l + (size_t)((KT_) * 64 + row) * 64 + fcol8);                 \
            cpa16(vb + row * 72 + fcol8,                                           \
                  Vg_h + (size_t)row * SEQ + (KT_) * 64 + fcol8);                  \
            cpa16(vb + KTS + row * 72 + fcol8,                                     \
                  Vg_l + (size_t)row * SEQ + (KT_) * 64 + fcol8);                  \
        }                                                                          \
        cpa_commit();                                                              \
    }

    FLASH_ISSUE(0, 0);

    // Q -> smem, pre-scaled by 1/8 (exact in bf16)
    const bf162 sc = __floats2bfloat162_rn(0.125f, 0.125f);
#pragma unroll
    for (int i = 0; i < 4; i++) {
        int c = tid + 256 * i;
        int row = c >> 3, col8 = (c & 7) * 8;
        uint4 vh = *(const uint4*)&Qg_h[row * 64 + col8];
        uint4 vl = *(const uint4*)&Qg_l[row * 64 + col8];
        bf162* ph = (bf162*)&vh;
        bf162* pl = (bf162*)&vl;
#pragma unroll
        for (int e = 0; e < 4; e++) { ph[e] = __hmul2(ph[e], sc); pl[e] = __hmul2(pl[e], sc); }
        *(uint4*)&Qh[row * 72 + col8] = vh;
        *(uint4*)&Ql[row * 72 + col8] = vl;
    }
    __syncthreads();

    // Q fragments -> registers (persist across all key tiles)
    unsigned qfh[4][4], qfl[4][4];
    {
        const int r = w * 16 + (lane >> 2);
#pragma unroll
        for (int kk = 0; kk < 4; kk++) {
            const int c0 = kk * 16 + (lane & 3) * 2;
            qfh[kk][0] = *(unsigned*)&Qh[r * 72 + c0];
            qfh[kk][1] = *(unsigned*)&Qh[(r + 8) * 72 + c0];
            qfh[kk][2] = *(unsigned*)&Qh[r * 72 + c0 + 8];
            qfh[kk][3] = *(unsigned*)&Qh[(r + 8) * 72 + c0 + 8];
            qfl[kk][0] = *(unsigned*)&Ql[r * 72 + c0];
            qfl[kk][1] = *(unsigned*)&Ql[(r + 8) * 72 + c0];
            qfl[kk][2] = *(unsigned*)&Ql[r * 72 + c0 + 8];
            qfl[kk][3] = *(unsigned*)&Ql[(r + 8) * 72 + c0 + 8];
        }
    }

    float o[8][4];
#pragma unroll
    for (int nt = 0; nt < 8; nt++)
#pragma unroll
        for (int e = 0; e < 4; e++) o[nt][e] = 0.f;
    float m0r = -1e30f, m1r = -1e30f, l0 = 0.f, l1 = 0.f;

    const int NKT = SEQ / 64;
    for (int kt = 0; kt < NKT; kt++) {
        if (kt + 1 < NKT) { FLASH_ISSUE(kt + 1, (kt + 1) & 1); cpa_wait<1>(); }
        else              { cpa_wait<0>(); }
        __syncthreads();

        const bf16* Kh = Kbuf + (kt & 1) * 2 * KTS;
        const bf16* Kl = Kh + KTS;
        const bf16* Vh = Vbuf + (kt & 1) * 2 * KTS;
        const bf16* Vl = Vh + KTS;

        // S = (Q/8) K^T
        float s[8][4];
#pragma unroll
        for (int nt = 0; nt < 8; nt++)
#pragma unroll
            for (int e = 0; e < 4; e++) s[nt][e] = 0.f;
#pragma unroll
        for (int kk = 0; kk < 4; kk++) {
            const int c0 = kk * 16 + (lane & 3) * 2;
#pragma unroll
            for (int nt = 0; nt < 8; nt++) {
                const int n = nt * 8 + (lane >> 2);
                unsigned b0h = *(const unsigned*)&Kh[n * 72 + c0];
                unsigned b1h = *(const unsigned*)&Kh[n * 72 + c0 + 8];
                unsigned b0l = *(const unsigned*)&Kl[n * 72 + c0];
                unsigned b1l = *(const unsigned*)&Kl[n * 72 + c0 + 8];
                mma_bf16(s[nt], qfh[kk], b0h, b1h);
                mma_bf16(s[nt], qfh[kk], b0l, b1l);
                mma_bf16(s[nt], qfl[kk], b0h, b1h);
            }
        }

        // online softmax (rows r=lane/4 and r+8); reduce across lane%4
        float tm0 = -1e30f, tm1 = -1e30f;
#pragma unroll
        for (int nt = 0; nt < 8; nt++) {
            tm0 = fmaxf(tm0, fmaxf(s[nt][0], s[nt][1]));
            tm1 = fmaxf(tm1, fmaxf(s[nt][2], s[nt][3]));
        }
        tm0 = fmaxf(tm0, __shfl_xor_sync(0xffffffffu, tm0, 1));
        tm0 = fmaxf(tm0, __shfl_xor_sync(0xffffffffu, tm0, 2));
        tm1 = fmaxf(tm1, __shfl_xor_sync(0xffffffffu, tm1, 1));
        tm1 = fmaxf(tm1, __shfl_xor_sync(0xffffffffu, tm1, 2));
        const float mn0 = fmaxf(m0r, tm0), mn1 = fmaxf(m1r, tm1);
        const float c0f = fexp(m0r - mn0), c1f = fexp(m1r - mn1);
        m0r = mn0; m1r = mn1;
        float ls0 = 0.f, ls1 = 0.f;
#pragma unroll
        for (int nt = 0; nt < 8; nt++) {
            s[nt][0] = fexp(s[nt][0] - mn0); ls0 += s[nt][0];
            s[nt][1] = fexp(s[nt][1] - mn0); ls0 += s[nt][1];
            s[nt][2] = fexp(s[nt][2] - mn1); ls1 += s[nt][2];
            s[nt][3] = fexp(s[nt][3] - mn1); ls1 += s[nt][3];
        }
        ls0 += __shfl_xor_sync(0xffffffffu, ls0, 1);
        ls0 += __shfl_xor_sync(0xffffffffu, ls0, 2);
        ls1 += __shfl_xor_sync(0xffffffffu, ls1, 1);
        ls1 += __shfl_xor_sync(0xffffffffu, ls1, 2);
        l0 = l0 * c0f + ls0;
        l1 = l1 * c1f + ls1;
#pragma unroll
        for (int nt = 0; nt < 8; nt++) {
            o[nt][0] *= c0f; o[nt][1] *= c0f; o[nt][2] *= c1f; o[nt][3] *= c1f;
        }

        // O += P V  (P fragments built directly from S accumulators)
#pragma unroll
        for (int kk = 0; kk < 4; kk++) {
            const int t0 = 2 * kk, t1 = 2 * kk + 1;
            unsigned pa[4], pl[4];
            pa[0] = packf(s[t0][0], s[t0][1]);
            pa[1] = packf(s[t0][2], s[t0][3]);
            pa[2] = packf(s[t1][0], s[t1][1]);
            pa[3] = packf(s[t1][2], s[t1][3]);
            pl[0] = packf(s[t0][0] - lo_f(pa[0]), s[t0][1] - hi_f(pa[0]));
            pl[1] = packf(s[t0][2] - lo_f(pa[1]), s[t0][3] - hi_f(pa[1]));
            pl[2] = packf(s[t1][0] - lo_f(pa[2]), s[t1][1] - hi_f(pa[2]));
            pl[3] = packf(s[t1][2] - lo_f(pa[3]), s[t1][3] - hi_f(pa[3]));
            const int c0 = kk * 16 + (lane & 3) * 2;
#pragma unroll
            for (int nt = 0; nt < 8; nt++) {
                const int n = nt * 8 + (lane >> 2);
                unsigned b0h = *(const unsigned*)&Vh[n * 72 + c0];
                unsigned b1h = *(const unsigned*)&Vh[n * 72 + c0 + 8];
                unsigned b0l = *(const unsigned*)&Vl[n * 72 + c0];
                unsigned b1l = *(const unsigned*)&Vl[n * 72 + c0 + 8];
                mma_bf16(o[nt], pa, b0h, b1h);
                mma_bf16(o[nt], pa, b0l, b1l);
                mma_bf16(o[nt], pl, b0h, b1h);
            }
        }
        __syncthreads();
    }

    // normalize + store split bf16 into [n][h*64+d]
    const float inv0 = 1.f / l0, inv1 = 1.f / l1;
    const int r = q0 + w * 16 + (lane >> 2);
#pragma unroll
    for (int nt = 0; nt < 8; nt++) {
        const int col = h * 64 + nt * 8 + (lane & 3) * 2;
        {
            float a = o[nt][0] * inv0, b = o[nt][1] * inv0;
            bf16 ha = __float2bfloat16_rn(a), hb = __float2bfloat16_rn(b);
            bf162 hh = __halves2bfloat162(ha, hb);
            *(unsigned*)&g_ah[(size_t)r * DIM + col] = *(unsigned*)&hh;
            *(unsigned*)&g_al[(size_t)r * DIM + col] =
                packf(a - __bfloat162float(ha), b - __bfloat162float(hb));
        }
        {
            float a = o[nt][2] * inv1, b = o[nt][3] * inv1;
            bf16 ha = __float2bfloat16_rn(a), hb = __float2bfloat16_rn(b);
            bf162 hh = __halves2bfloat162(ha, hb);
            *(unsigned*)&g_ah[(size_t)(r + 8) * DIM + col] = *(unsigned*)&hh;
            *(unsigned*)&g_al[(size_t)(r + 8) * DIM + col] =
                packf(a - __bfloat162float(ha), b - __bfloat162float(hb));
        }
    }
#undef FLASH_ISSUE
}

// ----------------------------------------------------------------------------
extern "C" void kernel_launch(void* const* d_in, const int* in_sizes, int n_in,
                              void* d_out, int out_size)
{
    (void)in_sizes; (void)n_in; (void)out_size;
    const float* x     = (const float*)d_in[0];
    const float* w_qkv = (const float*)d_in[1];
    const float* b_qkv = (const float*)d_in[2];
    const float* w_out = (const float*)d_in[3];
    const float* b_out = (const float*)d_in[4];
    float* out = (float*)d_out;

    bf16 *xh, *xl, *wqh, *wql, *woh, *wol, *ah, *al;
    cudaGetSymbolAddress((void**)&xh,  g_xh);  cudaGetSymbolAddress((void**)&xl,  g_xl);
    cudaGetSymbolAddress((void**)&wqh, g_wqh); cudaGetSymbolAddress((void**)&wql, g_wql);
    cudaGetSymbolAddress((void**)&woh, g_woh); cudaGetSymbolAddress((void**)&wol, g_wol);
    cudaGetSymbolAddress((void**)&ah,  g_ah);  cudaGetSymbolAddress((void**)&al,  g_al);

    const int gemm_smem = 2 * 4 * 128 * 40 * (int)sizeof(bf16);   // 81920
    cudaFuncSetAttribute(gemm_bf16x3<1, 3 * DIM, DIM>,
                         cudaFuncAttributeMaxDynamicSharedMemorySize, gemm_smem);
    cudaFuncSetAttribute(gemm_bf16x3<0, DIM, DIM>,
                         cudaFuncAttributeMaxDynamicSharedMemorySize, gemm_smem);

    // 0) fp32 -> split bf16
    split_kernel<<<(SEQ * DIM + 255) / 256, 256>>>(x, xh, xl, SEQ * DIM);
    split_kernel<<<(3 * DIM * DIM + 255) / 256, 256>>>(w_qkv, wqh, wql, 3 * DIM * DIM);
    split_kernel<<<(DIM * DIM + 255) / 256, 256>>>(w_out, woh, wol, DIM * DIM);

    // 1) QKV projection -> head-major Q,K + transposed V (split bf16)
    {
        dim3 grid(3 * DIM / 128, SEQ / 128);   // (18, 32)
        gemm_bf16x3<1, 3 * DIM, DIM><<<grid, 256, gemm_smem>>>(xh, xl, wqh, wql, b_qkv, nullptr);
    }

    // 2) flash attention
    {
        const int smem = (2 * 128 * 72 + 2 * 2 * 64 * 72 * 2) * (int)sizeof(bf16); // 110592
        cudaFuncSetAttribute(flash_mma,
                             cudaFuncAttributeMaxDynamicSharedMemorySize, smem);
        dim3 grid(SEQ / 128, NH);              // (32, 12)
        flash_mma<<<grid, 256, smem>>>();
    }

    // 3) output projection
    {
        dim3 grid(DIM / 128, SEQ / 128);       // (6, 32)
        gemm_bf16x3<0, DIM, DIM><<<grid, 256, gemm_smem>>>(ah, al, woh, wol, b_out, out);
    }
}